// round 14
// baseline (speedup 1.0000x reference)
#include <cuda_runtime.h>
#include <cuda_fp16.h>
#include <cstdint>

#define TT 4096
#define DD 1024
#define FF 2048
#define EE 8
#define NSM_CTAS 296   // 2 CTAs/SM * 148 SMs

// ---------------- scratch (no allocations allowed) ----------------
__device__ __half g_x16[TT * DD];               // x in fp16 (written by probe)
__device__ __half g_wup[EE * FF * DD];          // W_up fp16
__device__ __half g_wga[EE * FF * DD];          // W_gate fp16
__device__ __half g_wdn[EE * DD * FF];          // W_down fp16
__device__ __half g_h[(size_t)EE * TT * FF];    // h per expert (compact rows)
__device__ __half g_down[(size_t)EE * TT * DD]; // down per expert (compact rows, fp16)
__device__ float  g_scale[TT * EE];             // routing scale per (token, expert)
__device__ int    g_idx[EE * TT];               // compact token index lists
__device__ int    g_pos[TT * EE];               // token -> compact position (if active)
__device__ int    g_cnt[EE];                    // active token count per expert

// ---------------- small helpers ----------------
__device__ __forceinline__ uint32_t smem_u32(const void* p) {
    return (uint32_t)__cvta_generic_to_shared(p);
}
__device__ __forceinline__ void cp16(uint32_t s, const void* g) {
    asm volatile("cp.async.cg.shared.global [%0], [%1], 16;\n" :: "r"(s), "l"(g));
}
__device__ __forceinline__ void cp_commit() { asm volatile("cp.async.commit_group;\n"); }
template <int N>
__device__ __forceinline__ void cp_wait() { asm volatile("cp.async.wait_group %0;\n" :: "n"(N)); }

__device__ __forceinline__ void ldm4(uint32_t& r0, uint32_t& r1, uint32_t& r2, uint32_t& r3,
                                     uint32_t addr) {
    asm volatile("ldmatrix.sync.aligned.m8n8.x4.shared.b16 {%0,%1,%2,%3}, [%4];\n"
                 : "=r"(r0), "=r"(r1), "=r"(r2), "=r"(r3) : "r"(addr));
}
__device__ __forceinline__ void mma16816(float& d0, float& d1, float& d2, float& d3,
                                         uint32_t a0, uint32_t a1, uint32_t a2, uint32_t a3,
                                         uint32_t b0, uint32_t b1) {
    asm volatile("mma.sync.aligned.m16n8k16.row.col.f32.f16.f16.f32 "
                 "{%0,%1,%2,%3}, {%4,%5,%6,%7}, {%8,%9}, {%0,%1,%2,%3};\n"
                 : "+f"(d0), "+f"(d1), "+f"(d2), "+f"(d3)
                 : "r"(a0), "r"(a1), "r"(a2), "r"(a3), "r"(b0), "r"(b1));
}
__device__ __forceinline__ float silu_fast(float v) {
    return __fdividef(v, 1.f + __expf(-v));
}
// SW128 swizzle: XOR 16B-chunk index (bits[6:4]) with row-within-8 (bits[9:7])
__device__ __forceinline__ uint32_t sw128(uint32_t b) { return b ^ ((b >> 3) & 0x70); }

// ---------------- merged probe (512 blocks) + weight cvt (rest) ----------------
#define W16 (EE * FF * DD / 16)
#define PROBE_BLOCKS (TT / 8)
#define CVT_BLOCKS ((3 * W16 + 255) / 256)

__global__ void probe_cvt_kernel(const float* __restrict__ x, const float* __restrict__ Wp,
                                 const float* __restrict__ bp, const float* __restrict__ taub,
                                 const float* __restrict__ gam, const float* __restrict__ wdep,
                                 const float* __restrict__ wu, const float* __restrict__ wg,
                                 const float* __restrict__ wd) {
    if (blockIdx.x >= PROBE_BLOCKS) {
        // ---- weight conversion part ----
        long i = (long)(blockIdx.x - PROBE_BLOCKS) * blockDim.x + threadIdx.x;
        const float* src;
        __half* dst;
        long off;
        if (i < W16) { src = wu; dst = g_wup; off = i; }
        else if (i < 2 * W16) { src = wg; dst = g_wga; off = i - W16; }
        else if (i < 3 * W16) { src = wd; dst = g_wdn; off = i - 2 * W16; }
        else return;
        const float4* s4 = reinterpret_cast<const float4*>(src) + 4 * off;
        float4 v0 = s4[0], v1 = s4[1], v2 = s4[2], v3 = s4[3];
        __half2 a0 = __floats2half2_rn(v0.x, v0.y), a1 = __floats2half2_rn(v0.z, v0.w);
        __half2 b0 = __floats2half2_rn(v1.x, v1.y), b1 = __floats2half2_rn(v1.z, v1.w);
        __half2 c0 = __floats2half2_rn(v2.x, v2.y), c1 = __floats2half2_rn(v2.z, v2.w);
        __half2 d0 = __floats2half2_rn(v3.x, v3.y), d1 = __floats2half2_rn(v3.z, v3.w);
        uint4 o0, o1;
        o0.x = *reinterpret_cast<uint32_t*>(&a0); o0.y = *reinterpret_cast<uint32_t*>(&a1);
        o0.z = *reinterpret_cast<uint32_t*>(&b0); o0.w = *reinterpret_cast<uint32_t*>(&b1);
        o1.x = *reinterpret_cast<uint32_t*>(&c0); o1.y = *reinterpret_cast<uint32_t*>(&c1);
        o1.z = *reinterpret_cast<uint32_t*>(&d0); o1.w = *reinterpret_cast<uint32_t*>(&d1);
        uint4* p = reinterpret_cast<uint4*>(dst) + 2 * off;
        p[0] = o0;
        p[1] = o1;
        return;
    }
    // ---- probe part: one warp per token, all 8 experts; also emits x16 ----
    int t = blockIdx.x * (blockDim.x >> 5) + (threadIdx.x >> 5);
    int lane = threadIdx.x & 31;
    if (t >= TT) return;
    const float4* xr = reinterpret_cast<const float4*>(x + (size_t)t * DD);
    float4 xa[8];
#pragma unroll
    for (int j = 0; j < 8; j++) xa[j] = xr[lane + 32 * j];
    {
        uint2* xo = reinterpret_cast<uint2*>(g_x16 + (size_t)t * DD);
#pragma unroll
        for (int j = 0; j < 8; j++) {
            __half2 lo = __floats2half2_rn(xa[j].x, xa[j].y);
            __half2 hi = __floats2half2_rn(xa[j].z, xa[j].w);
            uint2 o;
            o.x = *reinterpret_cast<uint32_t*>(&lo);
            o.y = *reinterpret_cast<uint32_t*>(&hi);
            xo[lane + 32 * j] = o;
        }
    }
    float z = wdep[0] * 0.5f;                               // w_depth * depth_ratio
    float tau = taub[0] + gam[0] * (z / (1.f + expf(-z)));  // logit-space threshold
#pragma unroll
    for (int e = 0; e < EE; e++) {
        const float4* wr = reinterpret_cast<const float4*>(Wp + (size_t)e * DD);
        float acc = 0.f;
#pragma unroll
        for (int j = 0; j < 8; j++) {
            float4 b = wr[lane + 32 * j];
            acc += xa[j].x * b.x + xa[j].y * b.y + xa[j].z * b.z + xa[j].w * b.w;
        }
#pragma unroll
        for (int o = 16; o; o >>= 1) acc += __shfl_xor_sync(0xffffffffu, acc, o);
        if (lane == 0) {
            float logit = acc + bp[e];
            float s = (logit > tau) ? (1.f / (1.f + expf(-logit))) : 0.f;
            g_scale[t * EE + e] = s;
        }
    }
}

// ---------------- ordered per-expert compaction (deterministic) ----------------
__global__ void compact_kernel() {
    int e = blockIdx.x;
    __shared__ int warp_sums[8];
    __shared__ int s_base;
    int tid = threadIdx.x;
    int lane = tid & 31, wid = tid >> 5;
    if (tid == 0) s_base = 0;
    __syncthreads();
    for (int t0 = 0; t0 < TT; t0 += 256) {
        int t = t0 + tid;
        bool p = (g_scale[t * EE + e] != 0.f);
        unsigned m = __ballot_sync(0xffffffffu, p);
        int woff = __popc(m & ((1u << lane) - 1));
        if (lane == 0) warp_sums[wid] = __popc(m);
        __syncthreads();
        int base = s_base;
        for (int w = 0; w < wid; w++) base += warp_sums[w];
        if (p) {
            g_idx[e * TT + base + woff] = t;
            g_pos[t * EE + e] = base + woff;
        }
        __syncthreads();
        if (tid == 0) {
            int tot = 0;
            for (int w = 0; w < 8; w++) tot += warp_sums[w];
            s_base += tot;
        }
        __syncthreads();
    }
    if (tid == 0) g_cnt[e] = s_base;
}

// ========== GEMM common: BK=64 (128B rows, SW128 swizzle), 3-stage cp.async ==========
#define NSTG3 3

// ---------------- GEMM A: persistent CTAs, up/gate + SwiGLU fused ----------------
// Tile config (round-8, best measured): BM=128, BN=64, BK=64. 8 warps (4m x 2n), warp 32x32.
#define UG_STG 32768
#define UG_SMEM (UG_STG * NSTG3)
#define UG_NF (FF / 64)   // 32 f-tiles

__global__ __launch_bounds__(256) void gemm_ug_kernel() {
    extern __shared__ char smem_raw[];
    __shared__ int sIdx[128];
    const uint32_t sbase = smem_u32(smem_raw);
    const int tid = threadIdx.x;
    const int lane = tid & 31, wid = tid >> 5;
    const int wm = wid >> 1, wn = wid & 1;

    // per-expert tile counts (t-tiles * NF), deterministic flat schedule
    int ntile[EE], total = 0;
#pragma unroll
    for (int e = 0; e < EE; e++) {
        int nt = (g_cnt[e] + 127) >> 7;
        ntile[e] = nt * UG_NF;
        total += ntile[e];
    }

    for (int tile = blockIdx.x; tile < total; tile += gridDim.x) {
        int e = 0, rem = tile;
#pragma unroll
        for (int q = 0; q < EE; q++) {
            if (rem >= ntile[q]) { rem -= ntile[q]; e = q + 1; }
        }
        // e now = first expert where rem fits (scan semantics)
        // recompute cleanly:
        e = 0; rem = tile;
        while (rem >= ntile[e]) { rem -= ntile[e]; e++; }
        const int cnt = g_cnt[e];
        const int t0 = (rem / UG_NF) * 128;
        const int f0 = (rem % UG_NF) * 64;
        const __half* Wu = g_wup + (size_t)e * FF * DD;
        const __half* Wg = g_wga + (size_t)e * FF * DD;
        __half* hdst = g_h + (size_t)e * TT * FF;

        // ensure previous tile's smem reads are done before refilling
        cp_wait<0>();
        __syncthreads();
        if (tid < 128) {
            int r = t0 + tid;
            sIdx[tid] = g_idx[e * TT + (r < cnt ? r : cnt - 1)];
        }
        __syncthreads();

        float accU[2][4][4], accG[2][4][4];
#pragma unroll
        for (int a = 0; a < 2; a++)
#pragma unroll
            for (int b = 0; b < 4; b++)
#pragma unroll
                for (int c = 0; c < 4; c++) { accU[a][b][c] = 0.f; accG[a][b][c] = 0.f; }

        auto load_stage = [&](int s, int k0) {
            uint32_t sX = sbase + s * UG_STG;
            uint32_t sU = sX + 16384;
            uint32_t sG = sX + 24576;
#pragma unroll
            for (int q = 0; q < 4; q++) {
                int cid = tid + q * 256;
                int r = cid >> 3, ch = cid & 7;
                cp16(sX + sw128(r * 128 + ch * 16), g_x16 + (size_t)sIdx[r] * DD + k0 + ch * 8);
            }
#pragma unroll
            for (int q = 0; q < 2; q++) {
                int cid = tid + q * 256;
                int r = cid >> 3, ch = cid & 7;
                cp16(sU + sw128(r * 128 + ch * 16), Wu + (size_t)(f0 + r) * DD + k0 + ch * 8);
                cp16(sG + sw128(r * 128 + ch * 16), Wg + (size_t)(f0 + r) * DD + k0 + ch * 8);
            }
        };

        const int NK = DD / 64;  // 16
        load_stage(0, 0); cp_commit();
        load_stage(1, 64); cp_commit();

        for (int c = 0; c < NK; c++) {
            int buf = c % 3;
            uint32_t sX = sbase + buf * UG_STG;
            uint32_t sU = sX + 16384;
            uint32_t sG = sX + 24576;
            cp_wait<1>();
            __syncthreads();
#pragma unroll
            for (int kk = 0; kk < 4; kk++) {
                uint32_t a[2][4];
#pragma unroll
                for (int mi = 0; mi < 2; mi++) {
                    int row = wm * 32 + mi * 16 + (lane & 15);
                    int colb = kk * 32 + (lane >> 4) * 16;
                    ldm4(a[mi][0], a[mi][1], a[mi][2], a[mi][3], sX + sw128(row * 128 + colb));
                }
                uint32_t bu[4][2], bg[4][2];
#pragma unroll
                for (int nq = 0; nq < 2; nq++) {
                    int n = wn * 32 + nq * 16 + (lane & 7) + ((lane >> 4) << 3);
                    int kcolb = kk * 32 + ((lane >> 3) & 1) * 16;
                    uint32_t r0, r1, r2, r3;
                    ldm4(r0, r1, r2, r3, sU + sw128(n * 128 + kcolb));
                    bu[nq * 2][0] = r0; bu[nq * 2][1] = r1;
                    bu[nq * 2 + 1][0] = r2; bu[nq * 2 + 1][1] = r3;
                    ldm4(r0, r1, r2, r3, sG + sw128(n * 128 + kcolb));
                    bg[nq * 2][0] = r0; bg[nq * 2][1] = r1;
                    bg[nq * 2 + 1][0] = r2; bg[nq * 2 + 1][1] = r3;
                }
#pragma unroll
                for (int mi = 0; mi < 2; mi++)
#pragma unroll
                    for (int nj = 0; nj < 4; nj++) {
                        mma16816(accU[mi][nj][0], accU[mi][nj][1], accU[mi][nj][2], accU[mi][nj][3],
                                 a[mi][0], a[mi][1], a[mi][2], a[mi][3], bu[nj][0], bu[nj][1]);
                        mma16816(accG[mi][nj][0], accG[mi][nj][1], accG[mi][nj][2], accG[mi][nj][3],
                                 a[mi][0], a[mi][1], a[mi][2], a[mi][3], bg[nj][0], bg[nj][1]);
                    }
            }
            if (c + 2 < NK)
                load_stage((c + 2) % 3, (c + 2) * 64);
            cp_commit();
        }

        // epilogue: h = up * silu(gate), fp16 store to compact rows
        const int g = lane >> 2, tg = lane & 3;
#pragma unroll
        for (int mi = 0; mi < 2; mi++)
#pragma unroll
            for (int nj = 0; nj < 4; nj++) {
                int i0 = t0 + wm * 32 + mi * 16 + g;
                int col = f0 + wn * 32 + nj * 8 + tg * 2;
                float h0 = accU[mi][nj][0] * silu_fast(accG[mi][nj][0]);
                float h1 = accU[mi][nj][1] * silu_fast(accG[mi][nj][1]);
                float h2 = accU[mi][nj][2] * silu_fast(accG[mi][nj][2]);
                float h3 = accU[mi][nj][3] * silu_fast(accG[mi][nj][3]);
                if (i0 < cnt)
                    *reinterpret_cast<__half2*>(hdst + (size_t)i0 * FF + col) = __floats2half2_rn(h0, h1);
                if (i0 + 8 < cnt)
                    *reinterpret_cast<__half2*>(hdst + (size_t)(i0 + 8) * FF + col) = __floats2half2_rn(h2, h3);
            }
    }
}

// ---------------- GEMM B: persistent CTAs, down (compact rows, fp16 out) ----------------
// Tile config (round-10): BM=128, BN=128, BK=64, K=FF. 4 warps (2m x 2n), warp m64 x n64.
#define DN_STG 32768
#define DN_SMEM (DN_STG * NSTG3)
#define DN_NF (DD / 128)  // 8 d-tiles

__global__ __launch_bounds__(128) void gemm_dn_kernel() {
    extern __shared__ char smem_raw[];
    const uint32_t sbase = smem_u32(smem_raw);
    const int tid = threadIdx.x;
    const int lane = tid & 31, wid = tid >> 5;
    const int wm = wid >> 1, wn = wid & 1;  // 2m x 2n, warp 64x64

    int ntile[EE], total = 0;
#pragma unroll
    for (int e = 0; e < EE; e++) {
        int nt = (g_cnt[e] + 127) >> 7;
        ntile[e] = nt * DN_NF;
        total += ntile[e];
    }

    for (int tile = blockIdx.x; tile < total; tile += gridDim.x) {
        int e = 0, rem = tile;
        while (rem >= ntile[e]) { rem -= ntile[e]; e++; }
        const int cnt = g_cnt[e];
        const int t0 = (rem / DN_NF) * 128;
        const int d0c = (rem % DN_NF) * 128;
        const __half* Wd = g_wdn + (size_t)e * DD * FF;
        const __half* hsrc = g_h + (size_t)e * TT * FF;
        __half* ddst = g_down + (size_t)e * TT * DD;

        cp_wait<0>();
        __syncthreads();

        float acc[4][8][4];
#pragma unroll
        for (int a = 0; a < 4; a++)
#pragma unroll
            for (int b = 0; b < 8; b++)
#pragma unroll
                for (int c = 0; c < 4; c++) acc[a][b][c] = 0.f;

        auto load_stage = [&](int s, int k0) {
            uint32_t sH = sbase + s * DN_STG;
            uint32_t sW = sH + 16384;
#pragma unroll
            for (int q = 0; q < 8; q++) {
                int cid = tid + q * 128;
                int r = cid >> 3, ch = cid & 7;
                int ri = t0 + r;
                if (ri >= cnt) ri = cnt - 1;
                uint32_t so = sw128(r * 128 + ch * 16);
                cp16(sH + so, hsrc + (size_t)ri * FF + k0 + ch * 8);
                cp16(sW + so, Wd + (size_t)(d0c + r) * FF + k0 + ch * 8);
            }
        };

        const int NK = FF / 64;  // 32
        load_stage(0, 0); cp_commit();
        load_stage(1, 64); cp_commit();

        uint32_t a[2][4][4], bw[2][8][2];

        for (int c = 0; c < NK; c++) {
            int buf = c % 3;
            uint32_t sH = sbase + buf * DN_STG;
            uint32_t sW = sH + 16384;
            cp_wait<1>();
            __syncthreads();

            auto load_frags = [&](int slot, int kk) {
#pragma unroll
                for (int mi = 0; mi < 4; mi++) {
                    int row = wm * 64 + mi * 16 + (lane & 15);
                    int colb = kk * 32 + (lane >> 4) * 16;
                    ldm4(a[slot][mi][0], a[slot][mi][1], a[slot][mi][2], a[slot][mi][3],
                         sH + sw128(row * 128 + colb));
                }
#pragma unroll
                for (int nq = 0; nq < 4; nq++) {
                    int n = wn * 64 + nq * 16 + (lane & 7) + ((lane >> 4) << 3);
                    int kcolb = kk * 32 + ((lane >> 3) & 1) * 16;
                    uint32_t r0, r1, r2, r3;
                    ldm4(r0, r1, r2, r3, sW + sw128(n * 128 + kcolb));
                    bw[slot][nq * 2][0] = r0; bw[slot][nq * 2][1] = r1;
                    bw[slot][nq * 2 + 1][0] = r2; bw[slot][nq * 2 + 1][1] = r3;
                }
            };

            load_frags(0, 0);
#pragma unroll
            for (int kk = 0; kk < 4; kk++) {
                int cur = kk & 1;
                if (kk < 3) load_frags(cur ^ 1, kk + 1);
#pragma unroll
                for (int mi = 0; mi < 4; mi++)
#pragma unroll
                    for (int nj = 0; nj < 8; nj++)
                        mma16816(acc[mi][nj][0], acc[mi][nj][1], acc[mi][nj][2], acc[mi][nj][3],
                                 a[cur][mi][0], a[cur][mi][1], a[cur][mi][2], a[cur][mi][3],
                                 bw[cur][nj][0], bw[cur][nj][1]);
            }
            if (c + 2 < NK)
                load_stage((c + 2) % 3, (c + 2) * 64);
            cp_commit();
        }

        // epilogue: store unscaled down rows (compact, fp16)
        const int g = lane >> 2, tg = lane & 3;
#pragma unroll
        for (int mi = 0; mi < 4; mi++) {
            int i0 = t0 + wm * 64 + mi * 16 + g;
            int i1 = i0 + 8;
#pragma unroll
            for (int nj = 0; nj < 8; nj++) {
                int col = d0c + wn * 64 + nj * 8 + tg * 2;
                if (i0 < cnt) {
                    *reinterpret_cast<__half2*>(ddst + (size_t)i0 * DD + col) =
                        __floats2half2_rn(acc[mi][nj][0], acc[mi][nj][1]);
                }
                if (i1 < cnt) {
                    *reinterpret_cast<__half2*>(ddst + (size_t)i1 * DD + col) =
                        __floats2half2_rn(acc[mi][nj][2], acc[mi][nj][3]);
                }
            }
        }
    }
}

// ---------------- combine: out[t,:] = sum_e scale[t,e] * down[e][pos[t,e],:] ----------------
__global__ __launch_bounds__(256) void combine_kernel(float* __restrict__ out) {
    const int t = blockIdx.x;
    __shared__ float ss[EE];
    __shared__ int sp[EE];
    if (threadIdx.x < EE) {
        ss[threadIdx.x] = g_scale[t * EE + threadIdx.x];
        sp[threadIdx.x] = g_pos[t * EE + threadIdx.x];
    }
    __syncthreads();
    int d = threadIdx.x * 4;
    float acc0 = 0.f, acc1 = 0.f, acc2 = 0.f, acc3 = 0.f;
#pragma unroll
    for (int e = 0; e < EE; e++) {
        float s = ss[e];
        if (s != 0.f) {
            const __half2* p = reinterpret_cast<const __half2*>(
                g_down + ((size_t)e * TT + sp[e]) * DD + d);
            float2 v0 = __half22float2(p[0]);
            float2 v1 = __half22float2(p[1]);
            acc0 += s * v0.x;
            acc1 += s * v0.y;
            acc2 += s * v1.x;
            acc3 += s * v1.y;
        }
    }
    float4 o = make_float4(acc0, acc1, acc2, acc3);
    *reinterpret_cast<float4*>(out + (size_t)t * DD + d) = o;
}

// ---------------- launch ----------------
extern "C" void kernel_launch(void* const* d_in, const int* in_sizes, int n_in,
                              void* d_out, int out_size) {
    const float* x    = (const float*)d_in[0];
    const float* Wp   = (const float*)d_in[1];
    const float* bp   = (const float*)d_in[2];
    const float* Wu   = (const float*)d_in[3];
    const float* Wg   = (const float*)d_in[4];
    const float* Wd   = (const float*)d_in[5];
    const float* taub = (const float*)d_in[6];
    const float* gam  = (const float*)d_in[7];
    const float* wdep = (const float*)d_in[8];
    float* out = (float*)d_out;

    cudaFuncSetAttribute(gemm_ug_kernel, cudaFuncAttributeMaxDynamicSharedMemorySize, UG_SMEM);
    cudaFuncSetAttribute(gemm_dn_kernel, cudaFuncAttributeMaxDynamicSharedMemorySize, DN_SMEM);
    cudaFuncSetAttribute(gemm_ug_kernel, cudaFuncAttributePreferredSharedMemoryCarveout, 100);
    cudaFuncSetAttribute(gemm_dn_kernel, cudaFuncAttributePreferredSharedMemoryCarveout, 100);

    probe_cvt_kernel<<<PROBE_BLOCKS + CVT_BLOCKS, 256>>>(x, Wp, bp, taub, gam, wdep, Wu, Wg, Wd);
    compact_kernel<<<EE, 256>>>();

    gemm_ug_kernel<<<NSM_CTAS, 256, UG_SMEM>>>();
    gemm_dn_kernel<<<NSM_CTAS, 128, DN_SMEM>>>();
    combine_kernel<<<TT, 256>>>(out);
}

// round 15
// speedup vs baseline: 1.1139x; 1.1139x over previous
#include <cuda_runtime.h>
#include <cuda_fp16.h>
#include <cstdint>

#define TT 4096
#define DD 1024
#define FF 2048
#define EE 8

// ---------------- scratch (no allocations allowed) ----------------
__device__ __half g_x16[TT * DD];               // x in fp16 (written by probe)
__device__ __half g_wup[EE * FF * DD];          // W_up fp16
__device__ __half g_wga[EE * FF * DD];          // W_gate fp16
__device__ __half g_wdn[EE * DD * FF];          // W_down fp16
__device__ __half g_h[(size_t)EE * TT * FF];    // h per expert (compact rows)
__device__ __half g_down[(size_t)EE * TT * DD]; // down per expert (compact rows, fp16)
__device__ float  g_scale[TT * EE];             // routing scale per (token, expert)
__device__ int    g_idx[EE * TT];               // compact token index lists
__device__ int    g_pos[TT * EE];               // token -> compact position (if active)
__device__ int    g_cnt[EE];                    // active token count per expert

// ---------------- small helpers ----------------
__device__ __forceinline__ uint32_t smem_u32(const void* p) {
    return (uint32_t)__cvta_generic_to_shared(p);
}
__device__ __forceinline__ void cp16(uint32_t s, const void* g) {
    asm volatile("cp.async.cg.shared.global [%0], [%1], 16;\n" :: "r"(s), "l"(g));
}
__device__ __forceinline__ void cp_commit() { asm volatile("cp.async.commit_group;\n"); }
template <int N>
__device__ __forceinline__ void cp_wait() { asm volatile("cp.async.wait_group %0;\n" :: "n"(N)); }

__device__ __forceinline__ void ldm4(uint32_t& r0, uint32_t& r1, uint32_t& r2, uint32_t& r3,
                                     uint32_t addr) {
    asm volatile("ldmatrix.sync.aligned.m8n8.x4.shared.b16 {%0,%1,%2,%3}, [%4];\n"
                 : "=r"(r0), "=r"(r1), "=r"(r2), "=r"(r3) : "r"(addr));
}
__device__ __forceinline__ void mma16816(float& d0, float& d1, float& d2, float& d3,
                                         uint32_t a0, uint32_t a1, uint32_t a2, uint32_t a3,
                                         uint32_t b0, uint32_t b1) {
    asm volatile("mma.sync.aligned.m16n8k16.row.col.f32.f16.f16.f32 "
                 "{%0,%1,%2,%3}, {%4,%5,%6,%7}, {%8,%9}, {%0,%1,%2,%3};\n"
                 : "+f"(d0), "+f"(d1), "+f"(d2), "+f"(d3)
                 : "r"(a0), "r"(a1), "r"(a2), "r"(a3), "r"(b0), "r"(b1));
}
__device__ __forceinline__ float silu_fast(float v) {
    return __fdividef(v, 1.f + __expf(-v));
}
// SW128 swizzle: XOR 16B-chunk index (bits[6:4]) with row-within-8 (bits[9:7])
__device__ __forceinline__ uint32_t sw128(uint32_t b) { return b ^ ((b >> 3) & 0x70); }

// ---------------- merged probe (512 blocks) + weight cvt (rest), one launch ----------------
#define W16 (EE * FF * DD / 16)
#define PROBE_BLOCKS (TT / 8)
#define CVT_BLOCKS ((3 * W16 + 255) / 256)

__global__ void probe_cvt_kernel(const float* __restrict__ x, const float* __restrict__ Wp,
                                 const float* __restrict__ bp, const float* __restrict__ taub,
                                 const float* __restrict__ gam, const float* __restrict__ wdep,
                                 const float* __restrict__ wu, const float* __restrict__ wg,
                                 const float* __restrict__ wd) {
    if (blockIdx.x >= PROBE_BLOCKS) {
        // ---- weight conversion part ----
        long i = (long)(blockIdx.x - PROBE_BLOCKS) * blockDim.x + threadIdx.x;
        const float* src;
        __half* dst;
        long off;
        if (i < W16) { src = wu; dst = g_wup; off = i; }
        else if (i < 2 * W16) { src = wg; dst = g_wga; off = i - W16; }
        else if (i < 3 * W16) { src = wd; dst = g_wdn; off = i - 2 * W16; }
        else return;
        const float4* s4 = reinterpret_cast<const float4*>(src) + 4 * off;
        float4 v0 = s4[0], v1 = s4[1], v2 = s4[2], v3 = s4[3];
        __half2 a0 = __floats2half2_rn(v0.x, v0.y), a1 = __floats2half2_rn(v0.z, v0.w);
        __half2 b0 = __floats2half2_rn(v1.x, v1.y), b1 = __floats2half2_rn(v1.z, v1.w);
        __half2 c0 = __floats2half2_rn(v2.x, v2.y), c1 = __floats2half2_rn(v2.z, v2.w);
        __half2 d0 = __floats2half2_rn(v3.x, v3.y), d1 = __floats2half2_rn(v3.z, v3.w);
        uint4 o0, o1;
        o0.x = *reinterpret_cast<uint32_t*>(&a0); o0.y = *reinterpret_cast<uint32_t*>(&a1);
        o0.z = *reinterpret_cast<uint32_t*>(&b0); o0.w = *reinterpret_cast<uint32_t*>(&b1);
        o1.x = *reinterpret_cast<uint32_t*>(&c0); o1.y = *reinterpret_cast<uint32_t*>(&c1);
        o1.z = *reinterpret_cast<uint32_t*>(&d0); o1.w = *reinterpret_cast<uint32_t*>(&d1);
        uint4* p = reinterpret_cast<uint4*>(dst) + 2 * off;
        p[0] = o0;
        p[1] = o1;
        return;
    }
    // ---- probe part: one warp per token, all 8 experts; also emits x16 ----
    int t = blockIdx.x * (blockDim.x >> 5) + (threadIdx.x >> 5);
    int lane = threadIdx.x & 31;
    if (t >= TT) return;
    const float4* xr = reinterpret_cast<const float4*>(x + (size_t)t * DD);
    float4 xa[8];
#pragma unroll
    for (int j = 0; j < 8; j++) xa[j] = xr[lane + 32 * j];
    {
        uint2* xo = reinterpret_cast<uint2*>(g_x16 + (size_t)t * DD);
#pragma unroll
        for (int j = 0; j < 8; j++) {
            __half2 lo = __floats2half2_rn(xa[j].x, xa[j].y);
            __half2 hi = __floats2half2_rn(xa[j].z, xa[j].w);
            uint2 o;
            o.x = *reinterpret_cast<uint32_t*>(&lo);
            o.y = *reinterpret_cast<uint32_t*>(&hi);
            xo[lane + 32 * j] = o;
        }
    }
    float z = wdep[0] * 0.5f;                               // w_depth * depth_ratio
    float tau = taub[0] + gam[0] * (z / (1.f + expf(-z)));  // logit-space threshold
#pragma unroll
    for (int e = 0; e < EE; e++) {
        const float4* wr = reinterpret_cast<const float4*>(Wp + (size_t)e * DD);
        float acc = 0.f;
#pragma unroll
        for (int j = 0; j < 8; j++) {
            float4 b = wr[lane + 32 * j];
            acc += xa[j].x * b.x + xa[j].y * b.y + xa[j].z * b.z + xa[j].w * b.w;
        }
#pragma unroll
        for (int o = 16; o; o >>= 1) acc += __shfl_xor_sync(0xffffffffu, acc, o);
        if (lane == 0) {
            float logit = acc + bp[e];
            float s = (logit > tau) ? (1.f / (1.f + expf(-logit))) : 0.f;
            g_scale[t * EE + e] = s;
        }
    }
}

// ---------------- ordered per-expert compaction (deterministic) ----------------
__global__ void compact_kernel() {
    int e = blockIdx.x;
    __shared__ int warp_sums[8];
    __shared__ int s_base;
    int tid = threadIdx.x;
    int lane = tid & 31, wid = tid >> 5;
    if (tid == 0) s_base = 0;
    __syncthreads();
    for (int t0 = 0; t0 < TT; t0 += 256) {
        int t = t0 + tid;
        bool p = (g_scale[t * EE + e] != 0.f);
        unsigned m = __ballot_sync(0xffffffffu, p);
        int woff = __popc(m & ((1u << lane) - 1));
        if (lane == 0) warp_sums[wid] = __popc(m);
        __syncthreads();
        int base = s_base;
        for (int w = 0; w < wid; w++) base += warp_sums[w];
        if (p) {
            g_idx[e * TT + base + woff] = t;
            g_pos[t * EE + e] = base + woff;
        }
        __syncthreads();
        if (tid == 0) {
            int tot = 0;
            for (int w = 0; w < 8; w++) tot += warp_sums[w];
            s_base += tot;
        }
        __syncthreads();
    }
    if (tid == 0) g_cnt[e] = s_base;
}

// ========== GEMM common: BK=64 (128B rows, SW128 swizzle), 3-stage cp.async ==========
#define NSTG3 3

// ---------------- GEMM A: up/gate + SwiGLU fused (gathered rows), all experts ----------------
// Round-8 config (best measured): BM=128, BN=64, BK=64. 8 warps (4m x 2n), warp 32x32.
#define UG_STG 32768
#define UG_SMEM (UG_STG * NSTG3)

__global__ __launch_bounds__(256) void gemm_ug_kernel() {
    const int e = blockIdx.z;
    const int t0 = blockIdx.y * 128;
    const int cnt = g_cnt[e];
    if (t0 >= cnt) return;
    extern __shared__ char smem_raw[];
    __shared__ int sIdx[128];
    const uint32_t sbase = smem_u32(smem_raw);
    const int tid = threadIdx.x;
    const int lane = tid & 31, wid = tid >> 5;
    const int wm = wid >> 1, wn = wid & 1;
    const int f0 = blockIdx.x * 64;
    const __half* Wu = g_wup + (size_t)e * FF * DD;
    const __half* Wg = g_wga + (size_t)e * FF * DD;
    __half* hdst = g_h + (size_t)e * TT * FF;

    if (tid < 128) {
        int r = t0 + tid;
        sIdx[tid] = g_idx[e * TT + (r < cnt ? r : cnt - 1)];
    }
    __syncthreads();

    float accU[2][4][4], accG[2][4][4];
#pragma unroll
    for (int a = 0; a < 2; a++)
#pragma unroll
        for (int b = 0; b < 4; b++)
#pragma unroll
            for (int c = 0; c < 4; c++) { accU[a][b][c] = 0.f; accG[a][b][c] = 0.f; }

    auto load_stage = [&](int s, int k0) {
        uint32_t sX = sbase + s * UG_STG;
        uint32_t sU = sX + 16384;
        uint32_t sG = sX + 24576;
#pragma unroll
        for (int q = 0; q < 4; q++) {
            int cid = tid + q * 256;
            int r = cid >> 3, ch = cid & 7;
            cp16(sX + sw128(r * 128 + ch * 16), g_x16 + (size_t)sIdx[r] * DD + k0 + ch * 8);
        }
#pragma unroll
        for (int q = 0; q < 2; q++) {
            int cid = tid + q * 256;
            int r = cid >> 3, ch = cid & 7;
            cp16(sU + sw128(r * 128 + ch * 16), Wu + (size_t)(f0 + r) * DD + k0 + ch * 8);
            cp16(sG + sw128(r * 128 + ch * 16), Wg + (size_t)(f0 + r) * DD + k0 + ch * 8);
        }
    };

    const int NK = DD / 64;  // 16
    load_stage(0, 0); cp_commit();
    load_stage(1, 64); cp_commit();

    for (int c = 0; c < NK; c++) {
        int buf = c % 3;
        uint32_t sX = sbase + buf * UG_STG;
        uint32_t sU = sX + 16384;
        uint32_t sG = sX + 24576;
        cp_wait<1>();
        __syncthreads();
#pragma unroll
        for (int kk = 0; kk < 4; kk++) {
            uint32_t a[2][4];
#pragma unroll
            for (int mi = 0; mi < 2; mi++) {
                int row = wm * 32 + mi * 16 + (lane & 15);
                int colb = kk * 32 + (lane >> 4) * 16;
                ldm4(a[mi][0], a[mi][1], a[mi][2], a[mi][3], sX + sw128(row * 128 + colb));
            }
            uint32_t bu[4][2], bg[4][2];
#pragma unroll
            for (int nq = 0; nq < 2; nq++) {
                int n = wn * 32 + nq * 16 + (lane & 7) + ((lane >> 4) << 3);
                int kcolb = kk * 32 + ((lane >> 3) & 1) * 16;
                uint32_t r0, r1, r2, r3;
                ldm4(r0, r1, r2, r3, sU + sw128(n * 128 + kcolb));
                bu[nq * 2][0] = r0; bu[nq * 2][1] = r1;
                bu[nq * 2 + 1][0] = r2; bu[nq * 2 + 1][1] = r3;
                ldm4(r0, r1, r2, r3, sG + sw128(n * 128 + kcolb));
                bg[nq * 2][0] = r0; bg[nq * 2][1] = r1;
                bg[nq * 2 + 1][0] = r2; bg[nq * 2 + 1][1] = r3;
            }
#pragma unroll
            for (int mi = 0; mi < 2; mi++)
#pragma unroll
                for (int nj = 0; nj < 4; nj++) {
                    mma16816(accU[mi][nj][0], accU[mi][nj][1], accU[mi][nj][2], accU[mi][nj][3],
                             a[mi][0], a[mi][1], a[mi][2], a[mi][3], bu[nj][0], bu[nj][1]);
                    mma16816(accG[mi][nj][0], accG[mi][nj][1], accG[mi][nj][2], accG[mi][nj][3],
                             a[mi][0], a[mi][1], a[mi][2], a[mi][3], bg[nj][0], bg[nj][1]);
                }
        }
        if (c + 2 < NK)
            load_stage((c + 2) % 3, (c + 2) * 64);
        cp_commit();
    }

    // epilogue: h = up * silu(gate), fp16 store to compact rows
    const int g = lane >> 2, tg = lane & 3;
#pragma unroll
    for (int mi = 0; mi < 2; mi++)
#pragma unroll
        for (int nj = 0; nj < 4; nj++) {
            int i0 = t0 + wm * 32 + mi * 16 + g;
            int col = f0 + wn * 32 + nj * 8 + tg * 2;
            float h0 = accU[mi][nj][0] * silu_fast(accG[mi][nj][0]);
            float h1 = accU[mi][nj][1] * silu_fast(accG[mi][nj][1]);
            float h2 = accU[mi][nj][2] * silu_fast(accG[mi][nj][2]);
            float h3 = accU[mi][nj][3] * silu_fast(accG[mi][nj][3]);
            if (i0 < cnt)
                *reinterpret_cast<__half2*>(hdst + (size_t)i0 * FF + col) = __floats2half2_rn(h0, h1);
            if (i0 + 8 < cnt)
                *reinterpret_cast<__half2*>(hdst + (size_t)(i0 + 8) * FF + col) = __floats2half2_rn(h2, h3);
        }
}

// ---------------- GEMM B: down (compact rows, unscaled, fp16 out), all experts ----------------
// Round-10 config: BM=128, BN=128, BK=64, K=FF. 4 warps (2m x 2n), warp m64 x n64.
#define DN_STG 32768
#define DN_SMEM (DN_STG * NSTG3)

__global__ __launch_bounds__(128) void gemm_dn_kernel() {
    const int e = blockIdx.z;
    const int t0 = blockIdx.y * 128;
    const int cnt = g_cnt[e];
    if (t0 >= cnt) return;
    extern __shared__ char smem_raw[];
    const uint32_t sbase = smem_u32(smem_raw);
    const int tid = threadIdx.x;
    const int lane = tid & 31, wid = tid >> 5;
    const int wm = wid >> 1, wn = wid & 1;  // 2m x 2n, warp 64x64
    const int d0c = blockIdx.x * 128;
    const __half* Wd = g_wdn + (size_t)e * DD * FF;
    const __half* hsrc = g_h + (size_t)e * TT * FF;
    __half* ddst = g_down + (size_t)e * TT * DD;

    float acc[4][8][4];
#pragma unroll
    for (int a = 0; a < 4; a++)
#pragma unroll
        for (int b = 0; b < 8; b++)
#pragma unroll
            for (int c = 0; c < 4; c++) acc[a][b][c] = 0.f;

    auto load_stage = [&](int s, int k0) {
        uint32_t sH = sbase + s * DN_STG;
        uint32_t sW = sH + 16384;
#pragma unroll
        for (int q = 0; q < 8; q++) {
            int cid = tid + q * 128;
            int r = cid >> 3, ch = cid & 7;
            int ri = t0 + r;
            if (ri >= cnt) ri = cnt - 1;
            uint32_t so = sw128(r * 128 + ch * 16);
            cp16(sH + so, hsrc + (size_t)ri * FF + k0 + ch * 8);
            cp16(sW + so, Wd + (size_t)(d0c + r) * FF + k0 + ch * 8);
        }
    };

    const int NK = FF / 64;  // 32
    load_stage(0, 0); cp_commit();
    load_stage(1, 64); cp_commit();

    uint32_t a[2][4][4], bw[2][8][2];

    for (int c = 0; c < NK; c++) {
        int buf = c % 3;
        uint32_t sH = sbase + buf * DN_STG;
        uint32_t sW = sH + 16384;
        cp_wait<1>();
        __syncthreads();

        auto load_frags = [&](int slot, int kk) {
#pragma unroll
            for (int mi = 0; mi < 4; mi++) {
                int row = wm * 64 + mi * 16 + (lane & 15);
                int colb = kk * 32 + (lane >> 4) * 16;
                ldm4(a[slot][mi][0], a[slot][mi][1], a[slot][mi][2], a[slot][mi][3],
                     sH + sw128(row * 128 + colb));
            }
#pragma unroll
            for (int nq = 0; nq < 4; nq++) {
                int n = wn * 64 + nq * 16 + (lane & 7) + ((lane >> 4) << 3);
                int kcolb = kk * 32 + ((lane >> 3) & 1) * 16;
                uint32_t r0, r1, r2, r3;
                ldm4(r0, r1, r2, r3, sW + sw128(n * 128 + kcolb));
                bw[slot][nq * 2][0] = r0; bw[slot][nq * 2][1] = r1;
                bw[slot][nq * 2 + 1][0] = r2; bw[slot][nq * 2 + 1][1] = r3;
            }
        };

        load_frags(0, 0);
#pragma unroll
        for (int kk = 0; kk < 4; kk++) {
            int cur = kk & 1;
            if (kk < 3) load_frags(cur ^ 1, kk + 1);
#pragma unroll
            for (int mi = 0; mi < 4; mi++)
#pragma unroll
                for (int nj = 0; nj < 8; nj++)
                    mma16816(acc[mi][nj][0], acc[mi][nj][1], acc[mi][nj][2], acc[mi][nj][3],
                             a[cur][mi][0], a[cur][mi][1], a[cur][mi][2], a[cur][mi][3],
                             bw[cur][nj][0], bw[cur][nj][1]);
        }
        if (c + 2 < NK)
            load_stage((c + 2) % 3, (c + 2) * 64);
        cp_commit();
    }

    // epilogue: store unscaled down rows (compact, fp16)
    const int g = lane >> 2, tg = lane & 3;
#pragma unroll
    for (int mi = 0; mi < 4; mi++) {
        int i0 = t0 + wm * 64 + mi * 16 + g;
        int i1 = i0 + 8;
#pragma unroll
        for (int nj = 0; nj < 8; nj++) {
            int col = d0c + wn * 64 + nj * 8 + tg * 2;
            if (i0 < cnt) {
                *reinterpret_cast<__half2*>(ddst + (size_t)i0 * DD + col) =
                    __floats2half2_rn(acc[mi][nj][0], acc[mi][nj][1]);
            }
            if (i1 < cnt) {
                *reinterpret_cast<__half2*>(ddst + (size_t)i1 * DD + col) =
                    __floats2half2_rn(acc[mi][nj][2], acc[mi][nj][3]);
            }
        }
    }
}

// ---------------- combine: out[t,:] = sum_e scale[t,e] * down[e][pos[t,e],:] ----------------
__global__ __launch_bounds__(256) void combine_kernel(float* __restrict__ out) {
    const int t = blockIdx.x;
    __shared__ float ss[EE];
    __shared__ int sp[EE];
    if (threadIdx.x < EE) {
        ss[threadIdx.x] = g_scale[t * EE + threadIdx.x];
        sp[threadIdx.x] = g_pos[t * EE + threadIdx.x];
    }
    __syncthreads();
    int d = threadIdx.x * 4;
    float acc0 = 0.f, acc1 = 0.f, acc2 = 0.f, acc3 = 0.f;
#pragma unroll
    for (int e = 0; e < EE; e++) {
        float s = ss[e];
        if (s != 0.f) {
            const __half2* p = reinterpret_cast<const __half2*>(
                g_down + ((size_t)e * TT + sp[e]) * DD + d);
            float2 v0 = __half22float2(p[0]);
            float2 v1 = __half22float2(p[1]);
            acc0 += s * v0.x;
            acc1 += s * v0.y;
            acc2 += s * v1.x;
            acc3 += s * v1.y;
        }
    }
    float4 o = make_float4(acc0, acc1, acc2, acc3);
    *reinterpret_cast<float4*>(out + (size_t)t * DD + d) = o;
}

// ---------------- launch ----------------
extern "C" void kernel_launch(void* const* d_in, const int* in_sizes, int n_in,
                              void* d_out, int out_size) {
    const float* x    = (const float*)d_in[0];
    const float* Wp   = (const float*)d_in[1];
    const float* bp   = (const float*)d_in[2];
    const float* Wu   = (const float*)d_in[3];
    const float* Wg   = (const float*)d_in[4];
    const float* Wd   = (const float*)d_in[5];
    const float* taub = (const float*)d_in[6];
    const float* gam  = (const float*)d_in[7];
    const float* wdep = (const float*)d_in[8];
    float* out = (float*)d_out;

    cudaFuncSetAttribute(gemm_ug_kernel, cudaFuncAttributeMaxDynamicSharedMemorySize, UG_SMEM);
    cudaFuncSetAttribute(gemm_dn_kernel, cudaFuncAttributeMaxDynamicSharedMemorySize, DN_SMEM);
    cudaFuncSetAttribute(gemm_ug_kernel, cudaFuncAttributePreferredSharedMemoryCarveout, 100);
    cudaFuncSetAttribute(gemm_dn_kernel, cudaFuncAttributePreferredSharedMemoryCarveout, 100);

    probe_cvt_kernel<<<PROBE_BLOCKS + CVT_BLOCKS, 256>>>(x, Wp, bp, taub, gam, wdep, Wu, Wg, Wd);
    compact_kernel<<<EE, 256>>>();

    gemm_ug_kernel<<<dim3(FF / 64, TT / 128, EE), 256, UG_SMEM>>>();
    gemm_dn_kernel<<<dim3(DD / 128, TT / 128, EE), 128, DN_SMEM>>>();
    combine_kernel<<<TT, 256>>>(out);
}

// round 16
// speedup vs baseline: 1.1438x; 1.0268x over previous
#include <cuda_runtime.h>
#include <cuda_fp16.h>
#include <cstdint>

#define TT 4096
#define DD 1024
#define FF 2048
#define EE 8

// ---------------- scratch (no allocations allowed) ----------------
__device__ __half g_x16[TT * DD];               // x in fp16 (written by probe)
__device__ __half g_wup[EE * FF * DD];          // W_up fp16
__device__ __half g_wga[EE * FF * DD];          // W_gate fp16
__device__ __half g_wdn[EE * DD * FF];          // W_down fp16
__device__ __half g_h[(size_t)EE * TT * FF];    // h per expert (compact rows)
__device__ __half g_down[(size_t)EE * TT * DD]; // down per expert (compact rows, fp16)
__device__ float  g_scale[TT * EE];             // routing scale per (token, expert)
__device__ int    g_idx[EE * TT];               // compact token index lists
__device__ int    g_pos[TT * EE];               // token -> compact position (if active)
__device__ int    g_cnt[EE];                    // active token count per expert

// ---------------- small helpers ----------------
__device__ __forceinline__ uint32_t smem_u32(const void* p) {
    return (uint32_t)__cvta_generic_to_shared(p);
}
__device__ __forceinline__ void cp16(uint32_t s, const void* g) {
    asm volatile("cp.async.cg.shared.global [%0], [%1], 16;\n" :: "r"(s), "l"(g));
}
__device__ __forceinline__ void cp_commit() { asm volatile("cp.async.commit_group;\n"); }
template <int N>
__device__ __forceinline__ void cp_wait() { asm volatile("cp.async.wait_group %0;\n" :: "n"(N)); }

__device__ __forceinline__ void ldm4(uint32_t& r0, uint32_t& r1, uint32_t& r2, uint32_t& r3,
                                     uint32_t addr) {
    asm volatile("ldmatrix.sync.aligned.m8n8.x4.shared.b16 {%0,%1,%2,%3}, [%4];\n"
                 : "=r"(r0), "=r"(r1), "=r"(r2), "=r"(r3) : "r"(addr));
}
__device__ __forceinline__ void mma16816(float& d0, float& d1, float& d2, float& d3,
                                         uint32_t a0, uint32_t a1, uint32_t a2, uint32_t a3,
                                         uint32_t b0, uint32_t b1) {
    asm volatile("mma.sync.aligned.m16n8k16.row.col.f32.f16.f16.f32 "
                 "{%0,%1,%2,%3}, {%4,%5,%6,%7}, {%8,%9}, {%0,%1,%2,%3};\n"
                 : "+f"(d0), "+f"(d1), "+f"(d2), "+f"(d3)
                 : "r"(a0), "r"(a1), "r"(a2), "r"(a3), "r"(b0), "r"(b1));
}
__device__ __forceinline__ float silu_fast(float v) {
    return __fdividef(v, 1.f + __expf(-v));
}
// SW128 swizzle: XOR 16B-chunk index (bits[6:4]) with row-within-8 (bits[9:7])
__device__ __forceinline__ uint32_t sw128(uint32_t b) { return b ^ ((b >> 3) & 0x70); }

// ---------------- fp32 -> fp16 conversion for the three weight tensors ----------------
#define W16 (EE * FF * DD / 16)

__global__ void cvt_w_kernel(const float* __restrict__ wu, const float* __restrict__ wg,
                             const float* __restrict__ wd) {
    long i = (long)blockIdx.x * blockDim.x + threadIdx.x;
    const float* src;
    __half* dst;
    long off;
    if (i < W16) { src = wu; dst = g_wup; off = i; }
    else if (i < 2 * W16) { src = wg; dst = g_wga; off = i - W16; }
    else if (i < 3 * W16) { src = wd; dst = g_wdn; off = i - 2 * W16; }
    else return;
    const float4* s4 = reinterpret_cast<const float4*>(src) + 4 * off;
    float4 v0 = s4[0], v1 = s4[1], v2 = s4[2], v3 = s4[3];
    __half2 a0 = __floats2half2_rn(v0.x, v0.y), a1 = __floats2half2_rn(v0.z, v0.w);
    __half2 b0 = __floats2half2_rn(v1.x, v1.y), b1 = __floats2half2_rn(v1.z, v1.w);
    __half2 c0 = __floats2half2_rn(v2.x, v2.y), c1 = __floats2half2_rn(v2.z, v2.w);
    __half2 d0 = __floats2half2_rn(v3.x, v3.y), d1 = __floats2half2_rn(v3.z, v3.w);
    uint4 o0, o1;
    o0.x = *reinterpret_cast<uint32_t*>(&a0); o0.y = *reinterpret_cast<uint32_t*>(&a1);
    o0.z = *reinterpret_cast<uint32_t*>(&b0); o0.w = *reinterpret_cast<uint32_t*>(&b1);
    o1.x = *reinterpret_cast<uint32_t*>(&c0); o1.y = *reinterpret_cast<uint32_t*>(&c1);
    o1.z = *reinterpret_cast<uint32_t*>(&d0); o1.w = *reinterpret_cast<uint32_t*>(&d1);
    uint4* p = reinterpret_cast<uint4*>(dst) + 2 * off;
    p[0] = o0;
    p[1] = o1;
}

// ---------------- probe: one warp per token, all 8 experts; also emits x16 ----------------
__global__ void probe_kernel(const float* __restrict__ x, const float* __restrict__ Wp,
                             const float* __restrict__ bp, const float* __restrict__ taub,
                             const float* __restrict__ gam, const float* __restrict__ wd) {
    int t = blockIdx.x * (blockDim.x >> 5) + (threadIdx.x >> 5);
    int lane = threadIdx.x & 31;
    if (t >= TT) return;
    const float4* xr = reinterpret_cast<const float4*>(x + (size_t)t * DD);
    float4 xa[8];
#pragma unroll
    for (int j = 0; j < 8; j++) xa[j] = xr[lane + 32 * j];
    // emit fp16 row (removes x from the cvt kernel)
    {
        uint2* xo = reinterpret_cast<uint2*>(g_x16 + (size_t)t * DD);
#pragma unroll
        for (int j = 0; j < 8; j++) {
            __half2 lo = __floats2half2_rn(xa[j].x, xa[j].y);
            __half2 hi = __floats2half2_rn(xa[j].z, xa[j].w);
            uint2 o;
            o.x = *reinterpret_cast<uint32_t*>(&lo);
            o.y = *reinterpret_cast<uint32_t*>(&hi);
            xo[lane + 32 * j] = o;
        }
    }
    float z = wd[0] * 0.5f;                                 // w_depth * depth_ratio
    float tau = taub[0] + gam[0] * (z / (1.f + expf(-z)));  // logit-space threshold
#pragma unroll
    for (int e = 0; e < EE; e++) {
        const float4* wr = reinterpret_cast<const float4*>(Wp + (size_t)e * DD);
        float acc = 0.f;
#pragma unroll
        for (int j = 0; j < 8; j++) {
            float4 b = wr[lane + 32 * j];
            acc += xa[j].x * b.x + xa[j].y * b.y + xa[j].z * b.z + xa[j].w * b.w;
        }
#pragma unroll
        for (int o = 16; o; o >>= 1) acc += __shfl_xor_sync(0xffffffffu, acc, o);
        if (lane == 0) {
            float logit = acc + bp[e];
            float s = (logit > tau) ? (1.f / (1.f + expf(-logit))) : 0.f;
            g_scale[t * EE + e] = s;
        }
    }
}

// ---------------- ordered per-expert compaction (deterministic), 1024 threads ----------------
__global__ __launch_bounds__(1024) void compact_kernel() {
    int e = blockIdx.x;
    __shared__ int warp_sums[32];
    __shared__ int s_base;
    int tid = threadIdx.x;
    int lane = tid & 31, wid = tid >> 5;
    if (tid == 0) s_base = 0;
    __syncthreads();
    for (int t0 = 0; t0 < TT; t0 += 1024) {
        int t = t0 + tid;
        bool p = (g_scale[t * EE + e] != 0.f);
        unsigned m = __ballot_sync(0xffffffffu, p);
        int woff = __popc(m & ((1u << lane) - 1));
        if (lane == 0) warp_sums[wid] = __popc(m);
        __syncthreads();
        int base = s_base;
        for (int w = 0; w < wid; w++) base += warp_sums[w];
        if (p) {
            g_idx[e * TT + base + woff] = t;
            g_pos[t * EE + e] = base + woff;
        }
        __syncthreads();
        if (tid == 0) {
            int tot = 0;
            for (int w = 0; w < 32; w++) tot += warp_sums[w];
            s_base += tot;
        }
        __syncthreads();
    }
    if (tid == 0) g_cnt[e] = s_base;
}

// ========== GEMM common: BK=64 (128B rows, SW128 swizzle), 3-stage cp.async ==========
#define NSTG3 3

// ---------------- GEMM A: up/gate + SwiGLU fused (gathered rows), all experts ----------------
// Round-8 config (best measured): BM=128, BN=64, BK=64. 8 warps (4m x 2n), warp 32x32.
#define UG_STG 32768
#define UG_SMEM (UG_STG * NSTG3)

__global__ __launch_bounds__(256) void gemm_ug_kernel() {
    const int e = blockIdx.z;
    const int t0 = blockIdx.y * 128;
    const int cnt = g_cnt[e];
    if (t0 >= cnt) return;
    extern __shared__ char smem_raw[];
    __shared__ int sIdx[128];
    const uint32_t sbase = smem_u32(smem_raw);
    const int tid = threadIdx.x;
    const int lane = tid & 31, wid = tid >> 5;
    const int wm = wid >> 1, wn = wid & 1;
    const int f0 = blockIdx.x * 64;
    const __half* Wu = g_wup + (size_t)e * FF * DD;
    const __half* Wg = g_wga + (size_t)e * FF * DD;
    __half* hdst = g_h + (size_t)e * TT * FF;

    if (tid < 128) {
        int r = t0 + tid;
        sIdx[tid] = g_idx[e * TT + (r < cnt ? r : cnt - 1)];
    }
    __syncthreads();

    float accU[2][4][4], accG[2][4][4];
#pragma unroll
    for (int a = 0; a < 2; a++)
#pragma unroll
        for (int b = 0; b < 4; b++)
#pragma unroll
            for (int c = 0; c < 4; c++) { accU[a][b][c] = 0.f; accG[a][b][c] = 0.f; }

    auto load_stage = [&](int s, int k0) {
        uint32_t sX = sbase + s * UG_STG;
        uint32_t sU = sX + 16384;
        uint32_t sG = sX + 24576;
#pragma unroll
        for (int q = 0; q < 4; q++) {
            int cid = tid + q * 256;
            int r = cid >> 3, ch = cid & 7;
            cp16(sX + sw128(r * 128 + ch * 16), g_x16 + (size_t)sIdx[r] * DD + k0 + ch * 8);
        }
#pragma unroll
        for (int q = 0; q < 2; q++) {
            int cid = tid + q * 256;
            int r = cid >> 3, ch = cid & 7;
            cp16(sU + sw128(r * 128 + ch * 16), Wu + (size_t)(f0 + r) * DD + k0 + ch * 8);
            cp16(sG + sw128(r * 128 + ch * 16), Wg + (size_t)(f0 + r) * DD + k0 + ch * 8);
        }
    };

    const int NK = DD / 64;  // 16
    load_stage(0, 0); cp_commit();
    load_stage(1, 64); cp_commit();

    for (int c = 0; c < NK; c++) {
        int buf = c % 3;
        uint32_t sX = sbase + buf * UG_STG;
        uint32_t sU = sX + 16384;
        uint32_t sG = sX + 24576;
        cp_wait<1>();
        __syncthreads();
#pragma unroll
        for (int kk = 0; kk < 4; kk++) {
            uint32_t a[2][4];
#pragma unroll
            for (int mi = 0; mi < 2; mi++) {
                int row = wm * 32 + mi * 16 + (lane & 15);
                int colb = kk * 32 + (lane >> 4) * 16;
                ldm4(a[mi][0], a[mi][1], a[mi][2], a[mi][3], sX + sw128(row * 128 + colb));
            }
            uint32_t bu[4][2], bg[4][2];
#pragma unroll
            for (int nq = 0; nq < 2; nq++) {
                int n = wn * 32 + nq * 16 + (lane & 7) + ((lane >> 4) << 3);
                int kcolb = kk * 32 + ((lane >> 3) & 1) * 16;
                uint32_t r0, r1, r2, r3;
                ldm4(r0, r1, r2, r3, sU + sw128(n * 128 + kcolb));
                bu[nq * 2][0] = r0; bu[nq * 2][1] = r1;
                bu[nq * 2 + 1][0] = r2; bu[nq * 2 + 1][1] = r3;
                ldm4(r0, r1, r2, r3, sG + sw128(n * 128 + kcolb));
                bg[nq * 2][0] = r0; bg[nq * 2][1] = r1;
                bg[nq * 2 + 1][0] = r2; bg[nq * 2 + 1][1] = r3;
            }
#pragma unroll
            for (int mi = 0; mi < 2; mi++)
#pragma unroll
                for (int nj = 0; nj < 4; nj++) {
                    mma16816(accU[mi][nj][0], accU[mi][nj][1], accU[mi][nj][2], accU[mi][nj][3],
                             a[mi][0], a[mi][1], a[mi][2], a[mi][3], bu[nj][0], bu[nj][1]);
                    mma16816(accG[mi][nj][0], accG[mi][nj][1], accG[mi][nj][2], accG[mi][nj][3],
                             a[mi][0], a[mi][1], a[mi][2], a[mi][3], bg[nj][0], bg[nj][1]);
                }
        }
        if (c + 2 < NK)
            load_stage((c + 2) % 3, (c + 2) * 64);
        cp_commit();
    }

    // epilogue: h = up * silu(gate), fp16 store to compact rows
    const int g = lane >> 2, tg = lane & 3;
#pragma unroll
    for (int mi = 0; mi < 2; mi++)
#pragma unroll
        for (int nj = 0; nj < 4; nj++) {
            int i0 = t0 + wm * 32 + mi * 16 + g;
            int col = f0 + wn * 32 + nj * 8 + tg * 2;
            float h0 = accU[mi][nj][0] * silu_fast(accG[mi][nj][0]);
            float h1 = accU[mi][nj][1] * silu_fast(accG[mi][nj][1]);
            float h2 = accU[mi][nj][2] * silu_fast(accG[mi][nj][2]);
            float h3 = accU[mi][nj][3] * silu_fast(accG[mi][nj][3]);
            if (i0 < cnt)
                *reinterpret_cast<__half2*>(hdst + (size_t)i0 * FF + col) = __floats2half2_rn(h0, h1);
            if (i0 + 8 < cnt)
                *reinterpret_cast<__half2*>(hdst + (size_t)(i0 + 8) * FF + col) = __floats2half2_rn(h2, h3);
        }
}

// ---------------- GEMM B: down (compact rows, unscaled, fp16 out), all experts ----------------
// Round-10 config: BM=128, BN=128, BK=64, K=FF. 4 warps (2m x 2n), warp m64 x n64.
#define DN_STG 32768
#define DN_SMEM (DN_STG * NSTG3)

__global__ __launch_bounds__(128) void gemm_dn_kernel() {
    const int e = blockIdx.z;
    const int t0 = blockIdx.y * 128;
    const int cnt = g_cnt[e];
    if (t0 >= cnt) return;
    extern __shared__ char smem_raw[];
    const uint32_t sbase = smem_u32(smem_raw);
    const int tid = threadIdx.x;
    const int lane = tid & 31, wid = tid >> 5;
    const int wm = wid >> 1, wn = wid & 1;  // 2m x 2n, warp 64x64
    const int d0c = blockIdx.x * 128;
    const __half* Wd = g_wdn + (size_t)e * DD * FF;
    const __half* hsrc = g_h + (size_t)e * TT * FF;
    __half* ddst = g_down + (size_t)e * TT * DD;

    float acc[4][8][4];
#pragma unroll
    for (int a = 0; a < 4; a++)
#pragma unroll
        for (int b = 0; b < 8; b++)
#pragma unroll
            for (int c = 0; c < 4; c++) acc[a][b][c] = 0.f;

    auto load_stage = [&](int s, int k0) {
        uint32_t sH = sbase + s * DN_STG;
        uint32_t sW = sH + 16384;
#pragma unroll
        for (int q = 0; q < 8; q++) {
            int cid = tid + q * 128;
            int r = cid >> 3, ch = cid & 7;
            int ri = t0 + r;
            if (ri >= cnt) ri = cnt - 1;
            uint32_t so = sw128(r * 128 + ch * 16);
            cp16(sH + so, hsrc + (size_t)ri * FF + k0 + ch * 8);
            cp16(sW + so, Wd + (size_t)(d0c + r) * FF + k0 + ch * 8);
        }
    };

    const int NK = FF / 64;  // 32
    load_stage(0, 0); cp_commit();
    load_stage(1, 64); cp_commit();

    uint32_t a[2][4][4], bw[2][8][2];

    for (int c = 0; c < NK; c++) {
        int buf = c % 3;
        uint32_t sH = sbase + buf * DN_STG;
        uint32_t sW = sH + 16384;
        cp_wait<1>();
        __syncthreads();

        auto load_frags = [&](int slot, int kk) {
#pragma unroll
            for (int mi = 0; mi < 4; mi++) {
                int row = wm * 64 + mi * 16 + (lane & 15);
                int colb = kk * 32 + (lane >> 4) * 16;
                ldm4(a[slot][mi][0], a[slot][mi][1], a[slot][mi][2], a[slot][mi][3],
                     sH + sw128(row * 128 + colb));
            }
#pragma unroll
            for (int nq = 0; nq < 4; nq++) {
                int n = wn * 64 + nq * 16 + (lane & 7) + ((lane >> 4) << 3);
                int kcolb = kk * 32 + ((lane >> 3) & 1) * 16;
                uint32_t r0, r1, r2, r3;
                ldm4(r0, r1, r2, r3, sW + sw128(n * 128 + kcolb));
                bw[slot][nq * 2][0] = r0; bw[slot][nq * 2][1] = r1;
                bw[slot][nq * 2 + 1][0] = r2; bw[slot][nq * 2 + 1][1] = r3;
            }
        };

        load_frags(0, 0);
#pragma unroll
        for (int kk = 0; kk < 4; kk++) {
            int cur = kk & 1;
            if (kk < 3) load_frags(cur ^ 1, kk + 1);
#pragma unroll
            for (int mi = 0; mi < 4; mi++)
#pragma unroll
                for (int nj = 0; nj < 8; nj++)
                    mma16816(acc[mi][nj][0], acc[mi][nj][1], acc[mi][nj][2], acc[mi][nj][3],
                             a[cur][mi][0], a[cur][mi][1], a[cur][mi][2], a[cur][mi][3],
                             bw[cur][nj][0], bw[cur][nj][1]);
        }
        if (c + 2 < NK)
            load_stage((c + 2) % 3, (c + 2) * 64);
        cp_commit();
    }

    // epilogue: store unscaled down rows (compact, fp16)
    const int g = lane >> 2, tg = lane & 3;
#pragma unroll
    for (int mi = 0; mi < 4; mi++) {
        int i0 = t0 + wm * 64 + mi * 16 + g;
        int i1 = i0 + 8;
#pragma unroll
        for (int nj = 0; nj < 8; nj++) {
            int col = d0c + wn * 64 + nj * 8 + tg * 2;
            if (i0 < cnt) {
                *reinterpret_cast<__half2*>(ddst + (size_t)i0 * DD + col) =
                    __floats2half2_rn(acc[mi][nj][0], acc[mi][nj][1]);
            }
            if (i1 < cnt) {
                *reinterpret_cast<__half2*>(ddst + (size_t)i1 * DD + col) =
                    __floats2half2_rn(acc[mi][nj][2], acc[mi][nj][3]);
            }
        }
    }
}

// ---------------- combine: 2 tokens per block, 8 floats per thread ----------------
__global__ __launch_bounds__(256) void combine_kernel(float* __restrict__ out) {
    const int tb = blockIdx.x * 2;        // first token of this block
    __shared__ float ss[2][EE];
    __shared__ int sp[2][EE];
    if (threadIdx.x < 16) {
        int which = threadIdx.x >> 3;
        int e = threadIdx.x & 7;
        int tt = tb + which;
        ss[which][e] = g_scale[tt * EE + e];
        sp[which][e] = g_pos[tt * EE + e];
    }
    __syncthreads();
    const int half = threadIdx.x >> 7;    // 0 or 1: which token
    const int tl = threadIdx.x & 127;     // lane within token
    const int t = tb + half;
    const int d = tl * 8;                 // 8 floats per thread
    float acc[8];
#pragma unroll
    for (int j = 0; j < 8; j++) acc[j] = 0.f;
#pragma unroll
    for (int e = 0; e < EE; e++) {
        float s = ss[half][e];
        if (s != 0.f) {
            const __half2* p = reinterpret_cast<const __half2*>(
                g_down + ((size_t)e * TT + sp[half][e]) * DD + d);
            // two 16B loads
            const uint2* p2 = reinterpret_cast<const uint2*>(p);
            uint2 q0 = __ldg(p2);
            uint2 q1 = __ldg(p2 + 1);
            __half2 h0 = *reinterpret_cast<__half2*>(&q0.x);
            __half2 h1 = *reinterpret_cast<__half2*>(&q0.y);
            __half2 h2 = *reinterpret_cast<__half2*>(&q1.x);
            __half2 h3 = *reinterpret_cast<__half2*>(&q1.y);
            float2 v0 = __half22float2(h0);
            float2 v1 = __half22float2(h1);
            float2 v2 = __half22float2(h2);
            float2 v3 = __half22float2(h3);
            acc[0] += s * v0.x; acc[1] += s * v0.y;
            acc[2] += s * v1.x; acc[3] += s * v1.y;
            acc[4] += s * v2.x; acc[5] += s * v2.y;
            acc[6] += s * v3.x; acc[7] += s * v3.y;
        }
    }
    float4* o = reinterpret_cast<float4*>(out + (size_t)t * DD + d);
    o[0] = make_float4(acc[0], acc[1], acc[2], acc[3]);
    o[1] = make_float4(acc[4], acc[5], acc[6], acc[7]);
}

// ---------------- launch ----------------
extern "C" void kernel_launch(void* const* d_in, const int* in_sizes, int n_in,
                              void* d_out, int out_size) {
    const float* x    = (const float*)d_in[0];
    const float* Wp   = (const float*)d_in[1];
    const float* bp   = (const float*)d_in[2];
    const float* Wu   = (const float*)d_in[3];
    const float* Wg   = (const float*)d_in[4];
    const float* Wd   = (const float*)d_in[5];
    const float* taub = (const float*)d_in[6];
    const float* gam  = (const float*)d_in[7];
    const float* wdep = (const float*)d_in[8];
    float* out = (float*)d_out;

    cudaFuncSetAttribute(gemm_ug_kernel, cudaFuncAttributeMaxDynamicSharedMemorySize, UG_SMEM);
    cudaFuncSetAttribute(gemm_dn_kernel, cudaFuncAttributeMaxDynamicSharedMemorySize, DN_SMEM);
    cudaFuncSetAttribute(gemm_ug_kernel, cudaFuncAttributePreferredSharedMemoryCarveout, 100);
    cudaFuncSetAttribute(gemm_dn_kernel, cudaFuncAttributePreferredSharedMemoryCarveout, 100);

    probe_kernel<<<TT / 8, 256>>>(x, Wp, bp, taub, gam, wdep);
    cvt_w_kernel<<<(unsigned)((3L * W16 + 255) / 256), 256>>>(Wu, Wg, Wd);
    compact_kernel<<<EE, 1024>>>();

    gemm_ug_kernel<<<dim3(FF / 64, TT / 128, EE), 256, UG_SMEM>>>();
    gemm_dn_kernel<<<dim3(DD / 128, TT / 128, EE), 128, DN_SMEM>>>();
    combine_kernel<<<TT / 2, 256>>>(out);
}